// round 1
// baseline (speedup 1.0000x reference)
#include <cuda_runtime.h>
#include <math.h>

#define NB 16
#define NH 16
#define NTOK 740
#define HD 32
#define CDIM 512
#define MROWS (NB * NTOK)            // 11840
#define BHND (NB * NH * NTOK * HD)   // 6062080

// ---------------- device scratch (allocation-free rule: __device__ globals) ----
__device__ float g_bias[NH * NTOK * NTOK + 256];  // [H,740,740] + pad for col overrun
__device__ float g_qkv[3 * BHND];                 // q | k | v, each [B,H,N,hd]
__device__ float g_att[MROWS * CDIM];             // attention out [B,N,C]

// ---------------- attention smem layout (floats) ----------------
#define SQ_OFF 0
#define SKT_OFF (SQ_OFF + 64 * 32)        // K^T tile [32][132]
#define SV_OFF (SKT_OFF + 32 * 132)       // V tile [128][36]
#define SP_OFF (SV_OFF + 128 * 36)        // P tile [64][132]
#define SM_OFF (SP_OFF + 64 * 132)
#define SL_OFF (SM_OFF + 64)
#define SC_OFF (SL_OFF + 64)
#define ATT_SMEM_FLOATS (SC_OFF + 64)     // 19520 floats = 78080 bytes

// =====================================================================
// Bias assembly: bias[h,i,j] from the 4 Swin blocks
// =====================================================================
__global__ void build_bias_kernel(const float* __restrict__ btt,   // bias_table_target [1849,16]
                                  const float* __restrict__ btm,   // bias_table_temp   [961,16]
                                  const float* __restrict__ ttt,   // temp_target_table [16,484,1]
                                  const float* __restrict__ tgt,   // target_temp_table [16,256,1]
                                  const float* __restrict__ ttl,   // temp_target_line  [16,1,256]
                                  const float* __restrict__ tgl)   // target_temp_line  [16,1,484]
{
    int p = blockIdx.x * 256 + threadIdx.x;
    if (p >= NTOK * NTOK) return;
    int h = blockIdx.y;
    int i = p / NTOK, j = p - i * NTOK;
    float v;
    if (i < 256) {
        if (j < 256) {  // temp_bias
            int ai = i >> 4, bi = i & 15, aj = j >> 4, bj = j & 15;
            int idx = (ai - aj + 15) * 31 + (bi - bj + 15);
            v = btm[idx * NH + h];
        } else {        // target_temp = table[h,i] + line[h,j-256]
            v = tgt[h * 256 + i] + tgl[h * 484 + (j - 256)];
        }
    } else {
        int i2 = i - 256;
        if (j < 256) {  // temp_target
            v = ttt[h * 484 + i2] + ttl[h * 256 + j];
        } else {        // target_bias
            int j2 = j - 256;
            int ai = i2 / 22, bi = i2 - ai * 22;
            int aj = j2 / 22, bj = j2 - aj * 22;
            int idx = (ai - aj + 21) * 43 + (bi - bj + 21);
            v = btt[idx * NH + h];
        }
    }
    g_bias[h * NTOK * NTOK + p] = v;
}

// =====================================================================
// QKV GEMM: x[11840,512] @ W_qkv[512,1536] + b, scatter to q/k/v [B,H,N,hd]
// 128x128x8 tile, 256 threads, 8x8 microtile
// =====================================================================
__global__ void __launch_bounds__(256) sgemm_qkv_kernel(
    const float* __restrict__ A, const float* __restrict__ W,
    const float* __restrict__ bias)
{
    __shared__ float As[8][128];
    __shared__ float Bs[8][128];
    const int K = 512, NN = 1536;
    int m0 = blockIdx.y * 128;
    int n0 = blockIdx.x * 128;
    int tid = threadIdx.x;
    int tx = tid & 15, ty = tid >> 4;

    float acc[8][8];
#pragma unroll
    for (int i = 0; i < 8; i++)
#pragma unroll
        for (int j = 0; j < 8; j++) acc[i][j] = 0.f;

    int arow = tid >> 1;
    int acol = (tid & 1) * 4;
    int brow = tid >> 5;
    int bcol = (tid & 31) * 4;
    int gm_a = m0 + arow;
    const float* Aptr = A + (size_t)gm_a * K + acol;
    const float* Wptr = W + (size_t)brow * NN + n0 + bcol;

    for (int k0 = 0; k0 < K; k0 += 8) {
        float4 av = make_float4(0.f, 0.f, 0.f, 0.f);
        if (gm_a < MROWS) av = *(const float4*)(Aptr + k0);
        float4 bv = *(const float4*)(Wptr + (size_t)k0 * NN);
        As[acol + 0][arow] = av.x;
        As[acol + 1][arow] = av.y;
        As[acol + 2][arow] = av.z;
        As[acol + 3][arow] = av.w;
        *(float4*)&Bs[brow][bcol] = bv;
        __syncthreads();
#pragma unroll
        for (int kk = 0; kk < 8; kk++) {
            float a[8], b[8];
            *(float4*)&a[0] = *(float4*)&As[kk][ty * 4];
            *(float4*)&a[4] = *(float4*)&As[kk][64 + ty * 4];
            *(float4*)&b[0] = *(float4*)&Bs[kk][tx * 4];
            *(float4*)&b[4] = *(float4*)&Bs[kk][64 + tx * 4];
#pragma unroll
            for (int i = 0; i < 8; i++)
#pragma unroll
                for (int j = 0; j < 8; j++) acc[i][j] += a[i] * b[j];
        }
        __syncthreads();
    }

    const float scale = 0.17677669529663687f;  // hd^-0.5
#pragma unroll
    for (int ih = 0; ih < 2; ih++) {
#pragma unroll
        for (int ii = 0; ii < 4; ii++) {
            int gm = m0 + ih * 64 + ty * 4 + ii;
            if (gm >= MROWS) continue;
            int bb = gm / NTOK;
            int n = gm - bb * NTOK;
#pragma unroll
            for (int jh = 0; jh < 2; jh++) {
                int c = n0 + jh * 64 + tx * 4;
                int s = c >> 9;
                int hh = (c >> 5) & 15;
                int d = c & 31;
                float4 bi = *(const float4*)(bias + c);
                float4 o;
                o.x = acc[ih * 4 + ii][jh * 4 + 0] + bi.x;
                o.y = acc[ih * 4 + ii][jh * 4 + 1] + bi.y;
                o.z = acc[ih * 4 + ii][jh * 4 + 2] + bi.z;
                o.w = acc[ih * 4 + ii][jh * 4 + 3] + bi.w;
                if (s == 0) { o.x *= scale; o.y *= scale; o.z *= scale; o.w *= scale; }
                *(float4*)(g_qkv + (size_t)s * BHND +
                           ((size_t)((bb * NH + hh) * NTOK + n)) * HD + d) = o;
            }
        }
    }
}

// =====================================================================
// Fused flash attention: per (b,h,q-tile of 64), stream 128-key tiles
// =====================================================================
__global__ void __launch_bounds__(256, 2) attn_kernel()
{
    extern __shared__ float sm[];
    float* sQ = sm + SQ_OFF;
    float* sKt = sm + SKT_OFF;
    float* sV = sm + SV_OFF;
    float* sP = sm + SP_OFF;
    float* sMx = sm + SM_OFF;
    float* sL = sm + SL_OFF;
    float* sC = sm + SC_OFF;

    int b = blockIdx.z, h = blockIdx.y;
    int q0 = blockIdx.x * 64;
    int tid = threadIdx.x;
    int tx = tid & 15, ty = tid >> 4;
    int kq = tx & 3, dg = tx >> 2;

    const float* Qg = g_qkv + (size_t)((b * NH + h) * NTOK) * HD;
    const float* Kg = Qg + BHND;
    const float* Vg = Qg + 2 * BHND;

    // load Q tile (clamped rows for the ragged last tile)
    {
        int r = tid >> 2;
        int c = (tid & 3) * 8;
        int qr = q0 + r;
        if (qr > NTOK - 1) qr = NTOK - 1;
        const float4* src = (const float4*)(Qg + (size_t)qr * HD + c);
        float4 v0 = src[0];
        float4 v1 = src[1];
        *(float4*)(sQ + r * 32 + c) = v0;
        *(float4*)(sQ + r * 32 + c + 4) = v1;
    }
    if (tid < 64) { sMx[tid] = -1e30f; sL[tid] = 0.f; }

    float O[4][8];
#pragma unroll
    for (int i = 0; i < 4; i++)
#pragma unroll
        for (int j = 0; j < 8; j++) O[i][j] = 0.f;

    for (int kt = 0; kt < 6; kt++) {
        int k0 = kt * 128;
        __syncthreads();
        // load K (transposed) + V tiles; zero-fill invalid keys
        {
            int kk = tid >> 1;
            int c0 = (tid & 1) * 16;
            int kg = k0 + kk;
            bool valid = kg < NTOK;
            float4 kvv[4], vvv[4];
            if (valid) {
                const float4* ks = (const float4*)(Kg + (size_t)kg * HD + c0);
                const float4* vs = (const float4*)(Vg + (size_t)kg * HD + c0);
#pragma unroll
                for (int i = 0; i < 4; i++) { kvv[i] = ks[i]; vvv[i] = vs[i]; }
            } else {
#pragma unroll
                for (int i = 0; i < 4; i++) {
                    kvv[i] = make_float4(0.f, 0.f, 0.f, 0.f);
                    vvv[i] = make_float4(0.f, 0.f, 0.f, 0.f);
                }
            }
#pragma unroll
            for (int i = 0; i < 4; i++) {
                int d = c0 + i * 4;
                sKt[(d + 0) * 132 + kk] = kvv[i].x;
                sKt[(d + 1) * 132 + kk] = kvv[i].y;
                sKt[(d + 2) * 132 + kk] = kvv[i].z;
                sKt[(d + 3) * 132 + kk] = kvv[i].w;
                *(float4*)(sV + kk * 36 + d) = vvv[i];
            }
        }
        __syncthreads();

        // ---- S = Q K^T (q pre-scaled) : thread tile 4 rows x 8 keys ----
        float acc[4][8];
#pragma unroll
        for (int i = 0; i < 4; i++)
#pragma unroll
            for (int j = 0; j < 8; j++) acc[i][j] = 0.f;
#pragma unroll
        for (int d4 = 0; d4 < 8; d4++) {
            float qv[16];
#pragma unroll
            for (int i = 0; i < 4; i++)
                *(float4*)&qv[i * 4] = *(float4*)(sQ + (ty * 4 + i) * 32 + d4 * 4);
#pragma unroll
            for (int dd = 0; dd < 4; dd++) {
                int d = d4 * 4 + dd;
                float kv[8];
                *(float4*)&kv[0] = *(float4*)(sKt + d * 132 + tx * 8);
                *(float4*)&kv[4] = *(float4*)(sKt + d * 132 + tx * 8 + 4);
#pragma unroll
                for (int i = 0; i < 4; i++)
#pragma unroll
                    for (int j = 0; j < 8; j++)
                        acc[i][j] += qv[i * 4 + dd] * kv[j];
            }
        }

        // ---- bias add + mask + online softmax ----
        int kvalid = NTOK - k0;
        float mnewA[4], corrA[4], psumA[4];
#pragma unroll
        for (int i = 0; i < 4; i++) {
            int r = ty * 4 + i;
            int qr = q0 + r;
            int qrc = qr < NTOK ? qr : NTOK - 1;
            const float* brow = g_bias + ((size_t)h * NTOK + qrc) * NTOK + k0 + tx * 8;
            float4 b0 = *(const float4*)brow;
            float4 b1 = *(const float4*)(brow + 4);
            acc[i][0] += b0.x; acc[i][1] += b0.y; acc[i][2] += b0.z; acc[i][3] += b0.w;
            acc[i][4] += b1.x; acc[i][5] += b1.y; acc[i][6] += b1.z; acc[i][7] += b1.w;
#pragma unroll
            for (int j = 0; j < 8; j++)
                if (tx * 8 + j >= kvalid) acc[i][j] = -1e30f;

            float mloc = acc[i][0];
#pragma unroll
            for (int j = 1; j < 8; j++) mloc = fmaxf(mloc, acc[i][j]);
#pragma unroll
            for (int off = 8; off >= 1; off >>= 1)
                mloc = fmaxf(mloc, __shfl_xor_sync(0xffffffffu, mloc, off));

            float mold = sMx[r];
            float mnew = fmaxf(mold, mloc);
            float psum = 0.f;
#pragma unroll
            for (int j = 0; j < 8; j++) {
                float p = __expf(acc[i][j] - mnew);
                acc[i][j] = p;
                psum += p;
            }
#pragma unroll
            for (int off = 8; off >= 1; off >>= 1)
                psum += __shfl_xor_sync(0xffffffffu, psum, off);
            mnewA[i] = mnew;
            corrA[i] = __expf(mold - mnew);
            psumA[i] = psum;
            *(float4*)(sP + r * 132 + tx * 8) =
                make_float4(acc[i][0], acc[i][1], acc[i][2], acc[i][3]);
            *(float4*)(sP + r * 132 + tx * 8 + 4) =
                make_float4(acc[i][4], acc[i][5], acc[i][6], acc[i][7]);
        }
        __syncwarp();
        if (tx == 0) {
#pragma unroll
            for (int i = 0; i < 4; i++) {
                int r = ty * 4 + i;
                sMx[r] = mnewA[i];
                sL[r] = sL[r] * corrA[i] + psumA[i];
                sC[r] = corrA[i];
            }
        }
        __syncthreads();

        // ---- O = O*corr + P@V : thread tile 4 rows x 8 dims over k-quarter ----
#pragma unroll
        for (int i = 0; i < 4; i++) {
            float c = sC[ty * 4 + i];
#pragma unroll
            for (int j = 0; j < 8; j++) O[i][j] *= c;
        }
#pragma unroll 4
        for (int k4 = 0; k4 < 32; k4++) {
            int k = k4 * 4 + kq;
            float pv[4];
#pragma unroll
            for (int i = 0; i < 4; i++) pv[i] = sP[(ty * 4 + i) * 132 + k];
            float vv[8];
            *(float4*)&vv[0] = *(float4*)(sV + k * 36 + dg * 8);
            *(float4*)&vv[4] = *(float4*)(sV + k * 36 + dg * 8 + 4);
#pragma unroll
            for (int i = 0; i < 4; i++)
#pragma unroll
                for (int j = 0; j < 8; j++) O[i][j] += pv[i] * vv[j];
        }
    }

    // reduce the 4 k-quarter partials (lanes differ only in kq = bits 0..1)
#pragma unroll
    for (int i = 0; i < 4; i++)
#pragma unroll
        for (int j = 0; j < 8; j++) {
            O[i][j] += __shfl_xor_sync(0xffffffffu, O[i][j], 1);
            O[i][j] += __shfl_xor_sync(0xffffffffu, O[i][j], 2);
        }
    if (kq == 0) {
#pragma unroll
        for (int i = 0; i < 4; i++) {
            int qr = q0 + ty * 4 + i;
            if (qr < NTOK) {
                float linv = 1.f / sL[ty * 4 + i];
                float4 o0, o1;
                o0.x = O[i][0] * linv; o0.y = O[i][1] * linv;
                o0.z = O[i][2] * linv; o0.w = O[i][3] * linv;
                o1.x = O[i][4] * linv; o1.y = O[i][5] * linv;
                o1.z = O[i][6] * linv; o1.w = O[i][7] * linv;
                float* dst = g_att + ((size_t)b * NTOK + qr) * CDIM + h * HD + dg * 8;
                *(float4*)dst = o0;
                *(float4*)(dst + 4) = o1;
            }
        }
    }
}

// =====================================================================
// Proj GEMM: g_att[11840,512] @ W_proj[512,512] + b_proj -> d_out
// =====================================================================
__global__ void __launch_bounds__(256) sgemm_proj_kernel(
    const float* __restrict__ W, const float* __restrict__ bias,
    float* __restrict__ out)
{
    __shared__ float As[8][128];
    __shared__ float Bs[8][128];
    const int K = 512, NN = 512;
    const float* A = g_att;
    int m0 = blockIdx.y * 128;
    int n0 = blockIdx.x * 128;
    int tid = threadIdx.x;
    int tx = tid & 15, ty = tid >> 4;

    float acc[8][8];
#pragma unroll
    for (int i = 0; i < 8; i++)
#pragma unroll
        for (int j = 0; j < 8; j++) acc[i][j] = 0.f;

    int arow = tid >> 1;
    int acol = (tid & 1) * 4;
    int brow = tid >> 5;
    int bcol = (tid & 31) * 4;
    int gm_a = m0 + arow;
    const float* Aptr = A + (size_t)gm_a * K + acol;
    const float* Wptr = W + (size_t)brow * NN + n0 + bcol;

    for (int k0 = 0; k0 < K; k0 += 8) {
        float4 av = make_float4(0.f, 0.f, 0.f, 0.f);
        if (gm_a < MROWS) av = *(const float4*)(Aptr + k0);
        float4 bv = *(const float4*)(Wptr + (size_t)k0 * NN);
        As[acol + 0][arow] = av.x;
        As[acol + 1][arow] = av.y;
        As[acol + 2][arow] = av.z;
        As[acol + 3][arow] = av.w;
        *(float4*)&Bs[brow][bcol] = bv;
        __syncthreads();
#pragma unroll
        for (int kk = 0; kk < 8; kk++) {
            float a[8], b[8];
            *(float4*)&a[0] = *(float4*)&As[kk][ty * 4];
            *(float4*)&a[4] = *(float4*)&As[kk][64 + ty * 4];
            *(float4*)&b[0] = *(float4*)&Bs[kk][tx * 4];
            *(float4*)&b[4] = *(float4*)&Bs[kk][64 + tx * 4];
#pragma unroll
            for (int i = 0; i < 8; i++)
#pragma unroll
                for (int j = 0; j < 8; j++) acc[i][j] += a[i] * b[j];
        }
        __syncthreads();
    }

#pragma unroll
    for (int ih = 0; ih < 2; ih++) {
#pragma unroll
        for (int ii = 0; ii < 4; ii++) {
            int gm = m0 + ih * 64 + ty * 4 + ii;
            if (gm >= MROWS) continue;
#pragma unroll
            for (int jh = 0; jh < 2; jh++) {
                int c = n0 + jh * 64 + tx * 4;
                float4 bi = *(const float4*)(bias + c);
                float4 o;
                o.x = acc[ih * 4 + ii][jh * 4 + 0] + bi.x;
                o.y = acc[ih * 4 + ii][jh * 4 + 1] + bi.y;
                o.z = acc[ih * 4 + ii][jh * 4 + 2] + bi.z;
                o.w = acc[ih * 4 + ii][jh * 4 + 3] + bi.w;
                *(float4*)(out + (size_t)gm * NN + c) = o;
            }
        }
    }
}

// =====================================================================
extern "C" void kernel_launch(void* const* d_in, const int* in_sizes, int n_in,
                              void* d_out, int out_size)
{
    const float* x    = (const float*)d_in[0];
    const float* Wqkv = (const float*)d_in[1];
    const float* bqkv = (const float*)d_in[2];
    const float* Wprj = (const float*)d_in[3];
    const float* bprj = (const float*)d_in[4];
    const float* btt  = (const float*)d_in[5];   // bias_table_target
    const float* btm  = (const float*)d_in[6];   // bias_table_temp
    const float* ttt  = (const float*)d_in[7];   // temp_target_table
    const float* tgt  = (const float*)d_in[8];   // target_temp_table
    const float* ttl  = (const float*)d_in[9];   // temp_target_line
    const float* tgl  = (const float*)d_in[10];  // target_temp_line
    float* out = (float*)d_out;

    cudaFuncSetAttribute(attn_kernel, cudaFuncAttributeMaxDynamicSharedMemorySize,
                         ATT_SMEM_FLOATS * 4);

    build_bias_kernel<<<dim3((NTOK * NTOK + 255) / 256, NH), 256>>>(
        btt, btm, ttt, tgt, ttl, tgl);
    sgemm_qkv_kernel<<<dim3(12, 93), 256>>>(x, Wqkv, bqkv);
    attn_kernel<<<dim3(12, NH, NB), 256, ATT_SMEM_FLOATS * 4>>>();
    sgemm_proj_kernel<<<dim3(4, 93), 256>>>(Wprj, bprj, out);
}

// round 4
// speedup vs baseline: 2.1249x; 2.1249x over previous
#include <cuda_runtime.h>
#include <cuda_bf16.h>
#include <cstdint>
#include <math.h>

#define NB 16
#define NH 16
#define NTOK 740
#define HD 32
#define CDIM 512
#define MROWS (NB * NTOK)            // 11840
#define BHND (NB * NH * NTOK * HD)   // 6062080
#define QK_SCALE 0.17677669529663687f

// ---------------- device scratch ----------------
__device__ __align__(16) float g_bias[NH * NTOK * NTOK + 256];
__device__ __align__(16) __nv_bfloat16 g_Ahi[MROWS * CDIM];   // x split / attn out
__device__ __align__(16) __nv_bfloat16 g_Alo[MROWS * CDIM];
__device__ __align__(16) __nv_bfloat16 g_Whi[3 * CDIM * CDIM]; // W_qkv^T [1536,512]
__device__ __align__(16) __nv_bfloat16 g_Wlo[3 * CDIM * CDIM];
__device__ __align__(16) __nv_bfloat16 g_Phi[CDIM * CDIM];     // W_proj^T [512,512]
__device__ __align__(16) __nv_bfloat16 g_Plo[CDIM * CDIM];
__device__ __align__(16) __nv_bfloat16 g_q_hi[BHND];
__device__ __align__(16) __nv_bfloat16 g_q_lo[BHND];
__device__ __align__(16) __nv_bfloat16 g_k_hi[BHND];
__device__ __align__(16) __nv_bfloat16 g_k_lo[BHND];
__device__ __align__(16) __nv_bfloat16 g_v_hi[BHND];
__device__ __align__(16) __nv_bfloat16 g_v_lo[BHND];

// ================= helpers (base-ISA only: mma.sync / ldmatrix) =================
__device__ __forceinline__ uint32_t smem_u32(const void* p) {
    uint32_t a;
    asm("{ .reg .u64 t; cvta.to.shared.u64 t, %1; cvt.u32.u64 %0, t; }" : "=r"(a) : "l"(p));
    return a;
}

__device__ __forceinline__ void mma16816(float c[4], const uint32_t a[4],
                                         uint32_t b0, uint32_t b1) {
    asm volatile(
        "mma.sync.aligned.m16n8k16.row.col.f32.bf16.bf16.f32 "
        "{%0,%1,%2,%3}, {%4,%5,%6,%7}, {%8,%9}, {%0,%1,%2,%3};"
        : "+f"(c[0]), "+f"(c[1]), "+f"(c[2]), "+f"(c[3])
        : "r"(a[0]), "r"(a[1]), "r"(a[2]), "r"(a[3]), "r"(b0), "r"(b1));
}

#define LDSM4(R0, R1, R2, R3, ADDR) \
    asm volatile("ldmatrix.sync.aligned.m8n8.x4.shared.b16 {%0,%1,%2,%3}, [%4];" \
        : "=r"(R0), "=r"(R1), "=r"(R2), "=r"(R3) : "r"(ADDR))

#define LDSM4T(R0, R1, R2, R3, ADDR) \
    asm volatile("ldmatrix.sync.aligned.m8n8.x4.trans.shared.b16 {%0,%1,%2,%3}, [%4];" \
        : "=r"(R0), "=r"(R1), "=r"(R2), "=r"(R3) : "r"(ADDR))

// split fp32 pair -> packed bf16 hi pair + lo (residual) pair
__device__ __forceinline__ void split_pack2(float f0, float f1,
                                            uint32_t& hi, uint32_t& lo) {
    __nv_bfloat16 h0 = __float2bfloat16(f0);
    __nv_bfloat16 h1 = __float2bfloat16(f1);
    __nv_bfloat162 hv(h0, h1);
    hi = *reinterpret_cast<uint32_t*>(&hv);
    __nv_bfloat162 lv(__float2bfloat16(f0 - __bfloat162float(h0)),
                      __float2bfloat16(f1 - __bfloat162float(h1)));
    lo = *reinterpret_cast<uint32_t*>(&lv);
}

__device__ __forceinline__ int imin(int a, int b) { return a < b ? a : b; }

// =====================================================================
// Bias assembly
// =====================================================================
__global__ void build_bias_kernel(const float* __restrict__ btt,
                                  const float* __restrict__ btm,
                                  const float* __restrict__ ttt,
                                  const float* __restrict__ tgt,
                                  const float* __restrict__ ttl,
                                  const float* __restrict__ tgl)
{
    int p = blockIdx.x * 256 + threadIdx.x;
    if (p >= NTOK * NTOK) return;
    int h = blockIdx.y;
    int i = p / NTOK, j = p - i * NTOK;
    float v;
    if (i < 256) {
        if (j < 256) {
            int ai = i >> 4, bi = i & 15, aj = j >> 4, bj = j & 15;
            int idx = (ai - aj + 15) * 31 + (bi - bj + 15);
            v = btm[idx * NH + h];
        } else {
            v = tgt[h * 256 + i] + tgl[h * 484 + (j - 256)];
        }
    } else {
        int i2 = i - 256;
        if (j < 256) {
            v = ttt[h * 484 + i2] + ttl[h * 256 + j];
        } else {
            int j2 = j - 256;
            int ai = i2 / 22, bi = i2 - ai * 22;
            int aj = j2 / 22, bj = j2 - aj * 22;
            int idx = (ai - aj + 21) * 43 + (bi - bj + 21);
            v = btt[idx * NH + h];
        }
    }
    g_bias[h * NTOK * NTOK + p] = v;
}

// =====================================================================
// fp32 -> (hi, lo) bf16 split, elementwise
// =====================================================================
__global__ void split_kernel(const float* __restrict__ in,
                             __nv_bfloat16* __restrict__ hi,
                             __nv_bfloat16* __restrict__ lo, int n4)
{
    int i = blockIdx.x * 256 + threadIdx.x;
    if (i >= n4) return;
    float4 v = ((const float4*)in)[i];
    uint32_t h0, l0, h1, l1;
    split_pack2(v.x, v.y, h0, l0);
    split_pack2(v.z, v.w, h1, l1);
    uint2* ph = (uint2*)hi;
    uint2* pl = (uint2*)lo;
    ph[i] = make_uint2(h0, h1);
    pl[i] = make_uint2(l0, l1);
}

// =====================================================================
// Transpose + split: W[K,NN] fp32 -> hi/lo[NN,K] bf16
// =====================================================================
__global__ void tsplit_kernel(const float* __restrict__ W,
                              __nv_bfloat16* __restrict__ hi,
                              __nv_bfloat16* __restrict__ lo, int K, int NN)
{
    __shared__ float t[32][33];
    int nb = blockIdx.x * 32, kb = blockIdx.y * 32;
    int tx = threadIdx.x, ty = threadIdx.y;
#pragma unroll
    for (int i = 0; i < 32; i += 8)
        t[ty + i][tx] = W[(size_t)(kb + ty + i) * NN + nb + tx];
    __syncthreads();
#pragma unroll
    for (int i = 0; i < 32; i += 8) {
        float v = t[tx][ty + i];
        __nv_bfloat16 h = __float2bfloat16(v);
        __nv_bfloat16 l = __float2bfloat16(v - __bfloat162float(h));
        size_t o = (size_t)(nb + ty + i) * K + kb + tx;
        hi[o] = h;
        lo[o] = l;
    }
}

// =====================================================================
// HMMA split-bf16 GEMM: C[128m x 128n] = A[.,512] @ B[.,512]^T (+bias)
// MODE 0: qkv epilogue -> q/k/v split-bf16 [B,H,N,hd], q scaled
// MODE 1: proj epilogue -> fp32 out
// 256 threads; warp grid 4m x 2n; warp tile 32m x 64n
// =====================================================================
template <int MODE>
__global__ void __launch_bounds__(256) gemm_mma_kernel(
    const __nv_bfloat16* __restrict__ Ahi, const __nv_bfloat16* __restrict__ Alo,
    const __nv_bfloat16* __restrict__ Bhi, const __nv_bfloat16* __restrict__ Blo,
    const float* __restrict__ bias, float* __restrict__ out)
{
    __shared__ __align__(16) __nv_bfloat16 sA[2][128 * 40];
    __shared__ __align__(16) __nv_bfloat16 sB[2][128 * 40];
    int tid = threadIdx.x, lane = tid & 31, wid = tid >> 5;
    int wm = wid >> 1, wn = wid & 1;
    int m0 = blockIdx.y * 128, n0 = blockIdx.x * 128;
    int qr = lane >> 2, qc2 = (lane & 3) * 2;

    float acc[16][4];
#pragma unroll
    for (int i = 0; i < 16; i++)
#pragma unroll
        for (int j = 0; j < 4; j++) acc[i][j] = 0.f;

    int r = tid >> 1, cb = (tid & 1) * 16;
    int arow = imin(m0 + r, MROWS - 1);
    int brow = n0 + r;
    const uint4* gA0 = (const uint4*)(Ahi + (size_t)arow * CDIM);
    const uint4* gA1 = (const uint4*)(Alo + (size_t)arow * CDIM);
    const uint4* gB0 = (const uint4*)(Bhi + (size_t)brow * CDIM);
    const uint4* gB1 = (const uint4*)(Blo + (size_t)brow * CDIM);
    uint32_t sAb = smem_u32(sA);
    uint32_t sBb = smem_u32(sB);

    for (int k0 = 0; k0 < CDIM; k0 += 32) {
        int kq = (k0 + cb) >> 3;
        uint4 va0 = gA0[kq], va0b = gA0[kq + 1];
        uint4 va1 = gA1[kq], va1b = gA1[kq + 1];
        uint4 vb0 = gB0[kq], vb0b = gB0[kq + 1];
        uint4 vb1 = gB1[kq], vb1b = gB1[kq + 1];
        if (k0) __syncthreads();
        *(uint4*)(&sA[0][r * 40 + cb]) = va0;
        *(uint4*)(&sA[0][r * 40 + cb + 8]) = va0b;
        *(uint4*)(&sA[1][r * 40 + cb]) = va1;
        *(uint4*)(&sA[1][r * 40 + cb + 8]) = va1b;
        *(uint4*)(&sB[0][r * 40 + cb]) = vb0;
        *(uint4*)(&sB[0][r * 40 + cb + 8]) = vb0b;
        *(uint4*)(&sB[1][r * 40 + cb]) = vb1;
        *(uint4*)(&sB[1][r * 40 + cb + 8]) = vb1b;
        __syncthreads();

#pragma unroll
        for (int kc = 0; kc < 2; kc++) {
            uint32_t ah[2][4], al[2][4];
#pragma unroll
            for (int mb = 0; mb < 2; mb++) {
                uint32_t ad = sAb +
                    ((wm * 32 + mb * 16 + (lane & 15)) * 40 + kc * 16 + (lane >> 4) * 8) * 2;
                LDSM4(ah[mb][0], ah[mb][1], ah[mb][2], ah[mb][3], ad);
                LDSM4(al[mb][0], al[mb][1], al[mb][2], al[mb][3], ad + 10240);
            }
#pragma unroll
            for (int jp = 0; jp < 4; jp++) {
                uint32_t bd = sBb +
                    ((wn * 64 + jp * 16 + (lane & 7) + ((lane >> 3) & 1) * 8) * 40 +
                     kc * 16 + (lane >> 4) * 8) * 2;
                uint32_t bh[4], bl[4];
                LDSM4(bh[0], bh[1], bh[2], bh[3], bd);
                LDSM4(bl[0], bl[1], bl[2], bl[3], bd + 10240);
#pragma unroll
                for (int mb = 0; mb < 2; mb++) {
                    float* c0 = acc[mb * 8 + jp * 2];
                    float* c1 = acc[mb * 8 + jp * 2 + 1];
                    mma16816(c0, ah[mb], bh[0], bh[2]);
                    mma16816(c0, al[mb], bh[0], bh[2]);
                    mma16816(c0, ah[mb], bl[0], bl[2]);
                    mma16816(c1, ah[mb], bh[1], bh[3]);
                    mma16816(c1, al[mb], bh[1], bh[3]);
                    mma16816(c1, ah[mb], bl[1], bl[3]);
                }
            }
        }
    }

    // ---------------- epilogue ----------------
#pragma unroll
    for (int mb = 0; mb < 2; mb++) {
        int gm0 = m0 + wm * 32 + mb * 16 + qr;
#pragma unroll
        for (int half = 0; half < 2; half++) {
            int gm = gm0 + half * 8;
            if (gm >= MROWS) continue;
            int bb = gm / NTOK;
            int nn = gm - bb * NTOK;
#pragma unroll
            for (int j = 0; j < 8; j++) {
                int col = n0 + wn * 64 + j * 8 + qc2;
                float v0 = acc[mb * 8 + j][half * 2 + 0];
                float v1 = acc[mb * 8 + j][half * 2 + 1];
                float2 bv = *(const float2*)(bias + col);
                v0 += bv.x;
                v1 += bv.y;
                if (MODE == 0) {
                    int s = col >> 9, hh = (col >> 5) & 15, d = col & 31;
                    if (s == 0) { v0 *= QK_SCALE; v1 *= QK_SCALE; }
                    uint32_t hi, lo;
                    split_pack2(v0, v1, hi, lo);
                    size_t idx = ((size_t)((bb * NH + hh) * NTOK + nn)) * HD + d;
                    __nv_bfloat16 *ph, *pl;
                    if (s == 0)      { ph = g_q_hi; pl = g_q_lo; }
                    else if (s == 1) { ph = g_k_hi; pl = g_k_lo; }
                    else             { ph = g_v_hi; pl = g_v_lo; }
                    *(uint32_t*)(ph + idx) = hi;
                    *(uint32_t*)(pl + idx) = lo;
                } else {
                    float2 o = make_float2(v0, v1);
                    *(float2*)(out + (size_t)gm * CDIM + col) = o;
                }
            }
        }
    }
}

// =====================================================================
// HMMA flash attention: q-tile 128 x key-tile 128, hd=32, split-bf16 x3
// grid (6, NH, NB), 256 threads (8 warps, 16 q-rows each)
// =====================================================================
#define ATT_SMEM_BYTES (3 * 2 * 128 * 40 * 2)   // Q,K,V x (hi,lo) x 128x40 bf16 = 61440

__global__ void __launch_bounds__(256) attn_mma_kernel()
{
    extern __shared__ __align__(16) __nv_bfloat16 smA[];
    __nv_bfloat16* sQ = smA;               // hi at +0, lo at +5120 elems
    __nv_bfloat16* sK = smA + 10240;
    __nv_bfloat16* sV = smA + 20480;
    uint32_t sQb = smem_u32(sQ);
    uint32_t sKb = smem_u32(sK);
    uint32_t sVb = smem_u32(sV);

    int b = blockIdx.z, h = blockIdx.y, q0 = blockIdx.x * 128;
    int tid = threadIdx.x, lane = tid & 31, wid = tid >> 5;
    int qr = lane >> 2, qc2 = (lane & 3) * 2;
    size_t ho = (size_t)((b * NH + h) * NTOK) * HD;

    // load Q tile (hi+lo), rows clamped
    {
        int r = tid >> 1, cb = (tid & 1) * 16, ci = cb >> 3;
        int gr = imin(q0 + r, NTOK - 1);
        const uint4* s0 = (const uint4*)(g_q_hi + ho + (size_t)gr * HD);
        const uint4* s1 = (const uint4*)(g_q_lo + ho + (size_t)gr * HD);
        *(uint4*)(sQ + r * 40 + cb) = s0[ci];
        *(uint4*)(sQ + r * 40 + cb + 8) = s0[ci + 1];
        *(uint4*)(sQ + 5120 + r * 40 + cb) = s1[ci];
        *(uint4*)(sQ + 5120 + r * 40 + cb + 8) = s1[ci + 1];
    }
    __syncthreads();

    // Q fragments, kept in registers for all 6 key tiles
    uint32_t qh[2][4], ql[2][4];
#pragma unroll
    for (int kc = 0; kc < 2; kc++) {
        uint32_t ad = sQb + ((wid * 16 + (lane & 15)) * 40 + kc * 16 + (lane >> 4) * 8) * 2;
        LDSM4(qh[kc][0], qh[kc][1], qh[kc][2], qh[kc][3], ad);
        LDSM4(ql[kc][0], ql[kc][1], ql[kc][2], ql[kc][3], ad + 10240);
    }

    float O[4][4];
#pragma unroll
    for (int i = 0; i < 4; i++)
#pragma unroll
        for (int j = 0; j < 4; j++) O[i][j] = 0.f;
    float mrow0 = -1e30f, mrow1 = -1e30f, lrow0 = 0.f, lrow1 = 0.f;

    int row0 = q0 + wid * 16 + qr;           // global q row (within batch-head)
    const float* bias0 = g_bias + ((size_t)h * NTOK + imin(row0, NTOK - 1)) * NTOK;
    const float* bias1 = g_bias + ((size_t)h * NTOK + imin(row0 + 8, NTOK - 1)) * NTOK;

    for (int kt = 0; kt < 6; kt++) {
        int k0 = kt * 128;
        if (kt) __syncthreads();
        // load K, V tiles (hi+lo)
        {
            int r = tid >> 1, cb = (tid & 1) * 16, ci = cb >> 3;
            int gr = imin(k0 + r, NTOK - 1);
            const uint4* kh = (const uint4*)(g_k_hi + ho + (size_t)gr * HD);
            const uint4* kl = (const uint4*)(g_k_lo + ho + (size_t)gr * HD);
            const uint4* vh = (const uint4*)(g_v_hi + ho + (size_t)gr * HD);
            const uint4* vl = (const uint4*)(g_v_lo + ho + (size_t)gr * HD);
            *(uint4*)(sK + r * 40 + cb) = kh[ci];
            *(uint4*)(sK + r * 40 + cb + 8) = kh[ci + 1];
            *(uint4*)(sK + 5120 + r * 40 + cb) = kl[ci];
            *(uint4*)(sK + 5120 + r * 40 + cb + 8) = kl[ci + 1];
            *(uint4*)(sV + r * 40 + cb) = vh[ci];
            *(uint4*)(sV + r * 40 + cb + 8) = vh[ci + 1];
            *(uint4*)(sV + 5120 + r * 40 + cb) = vl[ci];
            *(uint4*)(sV + 5120 + r * 40 + cb + 8) = vl[ci + 1];
        }
        __syncthreads();

        // ---- S = Q K^T (3-term split) ----
        float S[16][4];
#pragma unroll
        for (int i = 0; i < 16; i++)
#pragma unroll
            for (int j = 0; j < 4; j++) S[i][j] = 0.f;

#pragma unroll
        for (int kc = 0; kc < 2; kc++) {
#pragma unroll
            for (int jp = 0; jp < 8; jp++) {
                uint32_t bd = sKb +
                    ((jp * 16 + (lane & 7) + ((lane >> 3) & 1) * 8) * 40 +
                     kc * 16 + (lane >> 4) * 8) * 2;
                uint32_t bh[4], bl[4];
                LDSM4(bh[0], bh[1], bh[2], bh[3], bd);
                LDSM4(bl[0], bl[1], bl[2], bl[3], bd + 10240);
                float* c0 = S[jp * 2];
                float* c1 = S[jp * 2 + 1];
                mma16816(c0, qh[kc], bh[0], bh[2]);
                mma16816(c0, ql[kc], bh[0], bh[2]);
                mma16816(c0, qh[kc], bl[0], bl[2]);
                mma16816(c1, qh[kc], bh[1], bh[3]);
                mma16816(c1, ql[kc], bh[1], bh[3]);
                mma16816(c1, qh[kc], bl[1], bl[3]);
            }
        }

        // ---- bias + key mask ----
        int kv = NTOK - k0;
#pragma unroll
        for (int j = 0; j < 16; j++) {
            int c = j * 8 + qc2;
            float2 b0 = *(const float2*)(bias0 + k0 + c);
            float2 b1 = *(const float2*)(bias1 + k0 + c);
            S[j][0] += b0.x; S[j][1] += b0.y;
            S[j][2] += b1.x; S[j][3] += b1.y;
            if (c >= kv)     { S[j][0] = -1e30f; S[j][2] = -1e30f; }
            if (c + 1 >= kv) { S[j][1] = -1e30f; S[j][3] = -1e30f; }
        }

        // ---- online softmax ----
        float m0l = -1e30f, m1l = -1e30f;
#pragma unroll
        for (int j = 0; j < 16; j++) {
            m0l = fmaxf(m0l, fmaxf(S[j][0], S[j][1]));
            m1l = fmaxf(m1l, fmaxf(S[j][2], S[j][3]));
        }
        m0l = fmaxf(m0l, __shfl_xor_sync(0xffffffffu, m0l, 1));
        m0l = fmaxf(m0l, __shfl_xor_sync(0xffffffffu, m0l, 2));
        m1l = fmaxf(m1l, __shfl_xor_sync(0xffffffffu, m1l, 1));
        m1l = fmaxf(m1l, __shfl_xor_sync(0xffffffffu, m1l, 2));
        float mn0 = fmaxf(mrow0, m0l), mn1 = fmaxf(mrow1, m1l);
        float corr0 = __expf(mrow0 - mn0), corr1 = __expf(mrow1 - mn1);
        mrow0 = mn0; mrow1 = mn1;
        float s0 = 0.f, s1 = 0.f;
#pragma unroll
        for (int j = 0; j < 16; j++) {
            S[j][0] = __expf(S[j][0] - mn0); s0 += S[j][0];
            S[j][1] = __expf(S[j][1] - mn0); s0 += S[j][1];
            S[j][2] = __expf(S[j][2] - mn1); s1 += S[j][2];
            S[j][3] = __expf(S[j][3] - mn1); s1 += S[j][3];
        }
        s0 += __shfl_xor_sync(0xffffffffu, s0, 1);
        s0 += __shfl_xor_sync(0xffffffffu, s0, 2);
        s1 += __shfl_xor_sync(0xffffffffu, s1, 1);
        s1 += __shfl_xor_sync(0xffffffffu, s1, 2);
        lrow0 = lrow0 * corr0 + s0;
        lrow1 = lrow1 * corr1 + s1;
#pragma unroll
        for (int jd = 0; jd < 4; jd++) {
            O[jd][0] *= corr0; O[jd][1] *= corr0;
            O[jd][2] *= corr1; O[jd][3] *= corr1;
        }

        // ---- O += P V (P from S fragments, split-bf16 x3) ----
#pragma unroll
        for (int kc = 0; kc < 8; kc++) {
            uint32_t pah[4], pal[4];
            split_pack2(S[2 * kc][0], S[2 * kc][1], pah[0], pal[0]);
            split_pack2(S[2 * kc][2], S[2 * kc][3], pah[1], pal[1]);
            split_pack2(S[2 * kc + 1][0], S[2 * kc + 1][1], pah[2], pal[2]);
            split_pack2(S[2 * kc + 1][2], S[2 * kc + 1][3], pah[3], pal[3]);
            uint32_t vrow = kc * 16 + (lane & 7) + ((lane >> 3) & 1) * 8;
            uint32_t vcb = (lane >> 4) * 8;
            uint32_t vd0 = sVb + (vrow * 40 + vcb) * 2;
            uint32_t vd1 = sVb + (vrow * 40 + 16 + vcb) * 2;
            uint32_t vh[8], vl[8];
            LDSM4T(vh[0], vh[1], vh[2], vh[3], vd0);
            LDSM4T(vh[4], vh[5], vh[6], vh[7], vd1);
            LDSM4T(vl[0], vl[1], vl[2], vl[3], vd0 + 10240);
            LDSM4T(vl[4], vl[5], vl[6], vl[7], vd1 + 10240);
            mma16816(O[0], pah, vh[0], vh[1]);
            mma16816(O[0], pal, vh[0], vh[1]);
            mma16816(O[0], pah, vl[0], vl[1]);
            mma16816(O[1], pah, vh[2], vh[3]);
            mma16816(O[1], pal, vh[2], vh[3]);
            mma16816(O[1], pah, vl[2], vl[3]);
            mma16816(O[2], pah, vh[4], vh[5]);
            mma16816(O[2], pal, vh[4], vh[5]);
            mma16816(O[2], pah, vl[4], vl[5]);
            mma16816(O[3], pah, vh[6], vh[7]);
            mma16816(O[3], pal, vh[6], vh[7]);
            mma16816(O[3], pah, vl[6], vl[7]);
        }
    }

    // ---- output: normalize, split to bf16 hi/lo for proj GEMM ----
    float li0 = 1.f / lrow0, li1 = 1.f / lrow1;
#pragma unroll
    for (int jd = 0; jd < 4; jd++) {
        int d = jd * 8 + qc2;
        if (row0 < NTOK) {
            uint32_t hi, lo;
            split_pack2(O[jd][0] * li0, O[jd][1] * li0, hi, lo);
            size_t idx = ((size_t)(b * NTOK + row0)) * CDIM + h * HD + d;
            *(uint32_t*)(g_Ahi + idx) = hi;
            *(uint32_t*)(g_Alo + idx) = lo;
        }
        if (row0 + 8 < NTOK) {
            uint32_t hi, lo;
            split_pack2(O[jd][2] * li1, O[jd][3] * li1, hi, lo);
            size_t idx = ((size_t)(b * NTOK + row0 + 8)) * CDIM + h * HD + d;
            *(uint32_t*)(g_Ahi + idx) = hi;
            *(uint32_t*)(g_Alo + idx) = lo;
        }
    }
}

// =====================================================================
extern "C" void kernel_launch(void* const* d_in, const int* in_sizes, int n_in,
                              void* d_out, int out_size)
{
    const float* x    = (const float*)d_in[0];
    const float* Wqkv = (const float*)d_in[1];
    const float* bqkv = (const float*)d_in[2];
    const float* Wprj = (const float*)d_in[3];
    const float* bprj = (const float*)d_in[4];
    const float* btt  = (const float*)d_in[5];
    const float* btm  = (const float*)d_in[6];
    const float* ttt  = (const float*)d_in[7];
    const float* tgt  = (const float*)d_in[8];
    const float* ttl  = (const float*)d_in[9];
    const float* tgl  = (const float*)d_in[10];
    float* out = (float*)d_out;

    cudaFuncSetAttribute(attn_mma_kernel, cudaFuncAttributeMaxDynamicSharedMemorySize,
                         ATT_SMEM_BYTES);

    __nv_bfloat16 *pAhi, *pAlo, *pWhi, *pWlo, *pPhi, *pPlo;
    cudaGetSymbolAddress((void**)&pAhi, g_Ahi);
    cudaGetSymbolAddress((void**)&pAlo, g_Alo);
    cudaGetSymbolAddress((void**)&pWhi, g_Whi);
    cudaGetSymbolAddress((void**)&pWlo, g_Wlo);
    cudaGetSymbolAddress((void**)&pPhi, g_Phi);
    cudaGetSymbolAddress((void**)&pPlo, g_Plo);

    const int n4 = MROWS * CDIM / 4;

    build_bias_kernel<<<dim3((NTOK * NTOK + 255) / 256, NH), 256>>>(
        btt, btm, ttt, tgt, ttl, tgl);
    split_kernel<<<(n4 + 255) / 256, 256>>>(x, pAhi, pAlo, n4);
    tsplit_kernel<<<dim3(1536 / 32, 512 / 32), dim3(32, 8)>>>(Wqkv, pWhi, pWlo, 512, 1536);
    tsplit_kernel<<<dim3(512 / 32, 512 / 32), dim3(32, 8)>>>(Wprj, pPhi, pPlo, 512, 512);
    gemm_mma_kernel<0><<<dim3(12, 93), 256>>>(pAhi, pAlo, pWhi, pWlo, bqkv, nullptr);
    attn_mma_kernel<<<dim3(6, NH, NB), 256, ATT_SMEM_BYTES>>>();
    gemm_mma_kernel<1><<<dim3(4, 93), 256>>>(pAhi, pAlo, pPhi, pPlo, bprj, out);
}